// round 2
// baseline (speedup 1.0000x reference)
#include <cuda_runtime.h>
#include <math.h>

// Problem constants
#define B_    64
#define L_    512
#define C_    1024
#define NT    7
#define START_ 5
#define STOP_  6
#define NROWS (B_ * L_)   // 32768

// Scratch (static device globals only — no allocs allowed)
__device__ float g_EE[NROWS * 8];   // exp(emissions), padded to 8 per row (1 MB)
__device__ float g_nll[B_];

// ---------------------------------------------------------------------------
// Kernel 1: pred = X @ W^T + b  (warp per row), fused epilogue:
//   - write pred to d_out[1+NROWS ...]
//   - write exp(pred) to g_EE (for exp-domain CRF)
//   - write labels as float to d_out[1 ...]
// ---------------------------------------------------------------------------
__global__ void __launch_bounds__(256) k1_gemm(
    const float* __restrict__ X, const int* __restrict__ labels,
    const float* __restrict__ W, const float* __restrict__ bias,
    float* __restrict__ out)
{
    __shared__ float sW[NT][C_];
    __shared__ float sb[8];
    for (int i = threadIdx.x; i < NT * C_; i += 256) sW[i / C_][i % C_] = W[i];
    if (threadIdx.x < NT) sb[threadIdx.x] = bias[threadIdx.x];
    __syncthreads();

    const int lane  = threadIdx.x & 31;
    const int gwarp = (blockIdx.x * blockDim.x + threadIdx.x) >> 5;
    const int nwarp = (gridDim.x * blockDim.x) >> 5;
    float* pred = out + 1 + NROWS;

    for (int row = gwarp; row < NROWS; row += nwarp) {
        const float4* xr = (const float4*)(X + (size_t)row * C_);
        float acc[NT] = {0.f, 0.f, 0.f, 0.f, 0.f, 0.f, 0.f};
        #pragma unroll
        for (int k = 0; k < 8; k++) {
            const int idx = lane + 32 * k;
            const float4 xv = xr[idx];
            #pragma unroll
            for (int t = 0; t < NT; t++) {
                const float4 wv = ((const float4*)sW[t])[idx];
                acc[t] = fmaf(xv.x, wv.x,
                          fmaf(xv.y, wv.y,
                           fmaf(xv.z, wv.z,
                            fmaf(xv.w, wv.w, acc[t]))));
            }
        }
        #pragma unroll
        for (int t = 0; t < NT; t++) {
            #pragma unroll
            for (int o = 16; o > 0; o >>= 1)
                acc[t] += __shfl_xor_sync(0xffffffffu, acc[t], o);
        }
        if (lane == 0) {
            float e[8];
            #pragma unroll
            for (int t = 0; t < NT; t++) {
                float v = acc[t] + sb[t];
                pred[(size_t)row * NT + t] = v;
                e[t] = expf(v);
            }
            e[7] = 0.f;
            float4* ee = (float4*)(g_EE + (size_t)row * 8);
            ee[0] = make_float4(e[0], e[1], e[2], e[3]);
            ee[1] = make_float4(e[4], e[5], e[6], e[7]);
        } else if (lane == 1) {
            out[1 + row] = (float)labels[row];
        }
    }
}

// ---------------------------------------------------------------------------
// Kernel 2: CRF forward in exp-domain (chunked matrix products) + gold score.
// One block per batch element; 128 threads = 16 chunks x 8 columns.
// ---------------------------------------------------------------------------
__global__ void __launch_bounds__(128) k2_crf(
    const float* __restrict__ trans,
    const int* __restrict__ labels,
    const float* __restrict__ outbuf)
{
    __shared__ float sEE[L_ * 8];       // 16 KB: exp-emissions for this batch
    __shared__ float sET[8][8];         // exp(transitions), padded
    __shared__ float sT[49];            // raw transitions
    __shared__ float sM[16][8][8];      // chunk matrices: [chunk][col][row]
    __shared__ float sS[16];            // chunk log-scales
    __shared__ float sv[8];
    __shared__ float sgold, svscale;

    const int b   = blockIdx.x;
    const int tid = threadIdx.x;

    {   // cooperative load of exp-emissions for this batch
        const float4* src = (const float4*)(g_EE + (size_t)b * L_ * 8);
        float4* dst = (float4*)sEE;
        for (int i = tid; i < L_ * 8 / 4; i += 128) dst[i] = src[i];
    }
    if (tid < 64) {
        int n = tid >> 3, p = tid & 7;
        sET[n][p] = (n < NT && p < NT) ? expf(trans[n * NT + p]) : 0.f;
    }
    if (tid < 49) sT[tid] = trans[tid];
    __syncthreads();

    // ---- Stage A: per-chunk matrix product (thread per column) ----
    {
        const int chunk = tid >> 3;     // 0..15
        const int col   = tid & 7;      // 0..7 (7 = zero pad column)
        float ET[NT][NT];
        #pragma unroll
        for (int n = 0; n < NT; n++)
            #pragma unroll
            for (int p = 0; p < NT; p++) ET[n][p] = sET[n][p];

        const int t0 = chunk * 32;
        float u[NT];
        #pragma unroll
        for (int n = 0; n < NT; n++)
            u[n] = (col < NT) ? sET[n][col] * sEE[t0 * 8 + n] : 0.f;
        float s = 0.f;

        for (int step = 1; step < 32; step++) {
            const float* ee = &sEE[(t0 + step) * 8];
            float v[NT];
            #pragma unroll
            for (int n = 0; n < NT; n++) {
                float a = ET[n][0] * u[0];
                #pragma unroll
                for (int p = 1; p < NT; p++) a = fmaf(ET[n][p], u[p], a);
                v[n] = a * ee[n];
            }
            #pragma unroll
            for (int n = 0; n < NT; n++) u[n] = v[n];

            if ((step & 7) == 7) {      // renormalize (shared scale per chunk)
                float m = u[0];
                #pragma unroll
                for (int n = 1; n < NT; n++) m = fmaxf(m, u[n]);
                m = fmaxf(m, __shfl_xor_sync(0xffffffffu, m, 1));
                m = fmaxf(m, __shfl_xor_sync(0xffffffffu, m, 2));
                m = fmaxf(m, __shfl_xor_sync(0xffffffffu, m, 4));
                if (m > 0.f) {
                    float inv = 1.f / m;
                    #pragma unroll
                    for (int n = 0; n < NT; n++) u[n] *= inv;
                    s += logf(m);
                }
            }
        }
        #pragma unroll
        for (int n = 0; n < NT; n++) sM[chunk][col][n] = u[n];
        sM[chunk][col][7] = 0.f;
        if (col == 0) sS[chunk] = s;
    }
    __syncthreads();

    // ---- Stage B: sequential matrix-vector combine (warp 0, lanes 0..7),
    //      gold score in parallel on warp 1 ----
    if (tid < 8) {
        const int n = tid;
        float v     = sM[0][START_][n];   // init vector = e_START
        float scale = sS[0];
        for (int c = 1; c < 16; c++) {
            sv[n] = v;
            __syncwarp(0x000000ffu);
            float a = 0.f;
            #pragma unroll
            for (int j = 0; j < NT; j++) a = fmaf(sM[c][j][n], sv[j], a);
            float m = a;
            m = fmaxf(m, __shfl_xor_sync(0xffu, m, 1));
            m = fmaxf(m, __shfl_xor_sync(0xffu, m, 2));
            m = fmaxf(m, __shfl_xor_sync(0xffu, m, 4));
            if (m > 0.f) { v = a / m; scale += logf(m); }
            else         { v = a; }
            scale += sS[c];
            __syncwarp(0x000000ffu);
        }
        sv[n] = v;
        if (n == 0) svscale = scale;
    } else if (tid >= 32 && tid < 64) {
        const int lane = tid - 32;
        const float* pred = outbuf + 1 + NROWS;
        const int base = b * L_;
        float acc = 0.f;
        #pragma unroll 4
        for (int k = 0; k < 16; k++) {
            int t   = lane + k * 32;
            int tag = labels[base + t];
            int pt  = (t == 0) ? START_ : labels[base + t - 1];
            acc += pred[(size_t)(base + t) * NT + tag] + sT[tag * NT + pt];
        }
        #pragma unroll
        for (int o = 16; o > 0; o >>= 1)
            acc += __shfl_xor_sync(0xffffffffu, acc, o);
        if (lane == 0) sgold = acc + sT[STOP_ * NT + labels[base + L_ - 1]];
    }
    __syncthreads();

    if (tid == 0) {
        float sum = 0.f;
        #pragma unroll
        for (int n = 0; n < NT; n++) sum += sv[n] * sET[STOP_][n];
        g_nll[b] = logf(sum) + svscale - sgold;
    }
}

// ---------------------------------------------------------------------------
// Kernel 3: deterministic sum of 64 per-batch NLLs -> d_out[0]
// ---------------------------------------------------------------------------
__global__ void k3_sum(float* __restrict__ out)
{
    __shared__ float s[64];
    int t = threadIdx.x;
    s[t] = g_nll[t];
    __syncthreads();
    #pragma unroll
    for (int o = 32; o > 0; o >>= 1) {
        if (t < o) s[t] += s[t + o];
        __syncthreads();
    }
    if (t == 0) out[0] = s[0];
}

extern "C" void kernel_launch(void* const* d_in, const int* in_sizes, int n_in,
                              void* d_out, int out_size)
{
    const float* X      = (const float*)d_in[0];
    const int*   labels = (const int*)  d_in[1];
    const float* W      = (const float*)d_in[2];
    const float* bias   = (const float*)d_in[3];
    const float* trans  = (const float*)d_in[4];
    float* out = (float*)d_out;

    k1_gemm<<<1024, 256>>>(X, labels, W, bias, out);
    k2_crf<<<B_, 128>>>(trans, labels, out);
    k3_sum<<<1, 64>>>(out);
}